// round 4
// baseline (speedup 1.0000x reference)
#include <cuda_runtime.h>
#include <cuda_bf16.h>
#include <cstdint>

// Problem dims (fixed per reference)
#define T_DIM 512
#define B_DIM 32
#define I_DIM 512
#define H_DIM 512
#define M_DIM (T_DIM * B_DIM)   // 16384
#define N_DIM (3 * H_DIM)       // 1536
#define K_DIM I_DIM             // 512

// ---------------------------------------------------------------------------
// Device scratch (no allocs allowed)
// ---------------------------------------------------------------------------
__device__ float         g_gx[(size_t)M_DIM * N_DIM];          // 100 MB
__device__ __nv_bfloat16 g_Ahi[(size_t)M_DIM * K_DIM];         // 16 MB
__device__ __nv_bfloat16 g_Alo[(size_t)M_DIM * K_DIM];         // 16 MB
__device__ __nv_bfloat16 g_Bhi[(size_t)N_DIM * K_DIM];         // 1.5 MB
__device__ __nv_bfloat16 g_Blo[(size_t)N_DIM * K_DIM];         // 1.5 MB

// ---------------------------------------------------------------------------
// PTX helpers (baseline-PTX features only: cp.async, ldmatrix, mma.sync)
// ---------------------------------------------------------------------------
__device__ __forceinline__ uint32_t smem_u32(const void* p) {
    uint32_t a;
    asm("{ .reg .u64 t; cvta.to.shared.u64 t, %1; cvt.u32.u64 %0, t; }"
        : "=r"(a) : "l"(p));
    return a;
}
__device__ __forceinline__ void cpa16(uint32_t dst, const void* src) {
    asm volatile("cp.async.cg.shared.global [%0], [%1], 16;"
                 :: "r"(dst), "l"(src));
}
__device__ __forceinline__ void cpa_commit() {
    asm volatile("cp.async.commit_group;" ::: "memory");
}
template <int N>
__device__ __forceinline__ void cpa_wait() {
    asm volatile("cp.async.wait_group %0;" :: "n"(N) : "memory");
}
__device__ __forceinline__ void ldm4(uint32_t* r, uint32_t addr) {
    asm volatile("ldmatrix.sync.aligned.m8n8.x4.shared.b16 {%0,%1,%2,%3}, [%4];"
                 : "=r"(r[0]), "=r"(r[1]), "=r"(r[2]), "=r"(r[3]) : "r"(addr));
}
__device__ __forceinline__ void mma_bf16(float* c, const uint32_t* a,
                                         const uint32_t* b) {
    asm volatile(
        "mma.sync.aligned.m16n8k16.row.col.f32.bf16.bf16.f32 "
        "{%0,%1,%2,%3}, {%4,%5,%6,%7}, {%8,%9}, {%0,%1,%2,%3};"
        : "+f"(c[0]), "+f"(c[1]), "+f"(c[2]), "+f"(c[3])
        : "r"(a[0]), "r"(a[1]), "r"(a[2]), "r"(a[3]), "r"(b[0]), "r"(b[1]));
}
__device__ __forceinline__ float ex2f(float x) {
    float y;
    asm("ex2.approx.f32 %0, %1;" : "=f"(y) : "f"(x));
    return y;
}
__device__ __forceinline__ float rcpf(float x) {
    float y;
    asm("rcp.approx.f32 %0, %1;" : "=f"(y) : "f"(x));
    return y;
}

// ---------------------------------------------------------------------------
// Split conversion: v -> bf16 hi + bf16 lo (residual)
// ---------------------------------------------------------------------------
__device__ __forceinline__ unsigned short f2b_split(float v, unsigned short& lo_out) {
    __nv_bfloat16 h = __float2bfloat16(v);
    float r = v - __bfloat162float(h);
    __nv_bfloat16 l = __float2bfloat16(r);
    lo_out = *reinterpret_cast<unsigned short*>(&l);
    return *reinterpret_cast<unsigned short*>(&h);
}

__global__ void convert_split_A(const float4* __restrict__ src) {
    ushort4* hi = reinterpret_cast<ushort4*>(g_Ahi);
    ushort4* lo = reinterpret_cast<ushort4*>(g_Alo);
    const int n4 = (M_DIM * K_DIM) / 4;
    const int stride = gridDim.x * blockDim.x;
    for (int i = blockIdx.x * blockDim.x + threadIdx.x; i < n4; i += stride) {
        float4 v = __ldcs(src + i);
        ushort4 h, l;
        h.x = f2b_split(v.x, l.x);
        h.y = f2b_split(v.y, l.y);
        h.z = f2b_split(v.z, l.z);
        h.w = f2b_split(v.w, l.w);
        hi[i] = h; lo[i] = l;
    }
}
__global__ void convert_split_B(const float4* __restrict__ src) {
    ushort4* hi = reinterpret_cast<ushort4*>(g_Bhi);
    ushort4* lo = reinterpret_cast<ushort4*>(g_Blo);
    const int n4 = (N_DIM * K_DIM) / 4;
    const int stride = gridDim.x * blockDim.x;
    for (int i = blockIdx.x * blockDim.x + threadIdx.x; i < n4; i += stride) {
        float4 v = __ldcs(src + i);
        ushort4 h, l;
        h.x = f2b_split(v.x, l.x);
        h.y = f2b_split(v.y, l.y);
        h.z = f2b_split(v.z, l.z);
        h.w = f2b_split(v.w, l.w);
        hi[i] = h; lo[i] = l;
    }
}

// ---------------------------------------------------------------------------
// HMMA GEMM: gx[m, n] = x[m, :] . W[n, :] via 3-pass bf16 split (mma.sync)
// CTA 128x256, 512 threads (16 warps, 2x8, warp tile 64x32), BK=32,
// 4-stage cp.async ring, one __syncthreads per stage.
// Smem rows 64 B, unpadded (conflict-free per 8-lane ldmatrix phase).
// ---------------------------------------------------------------------------
#define GBM 128
#define GBN 256
#define GBK 32
#define NSTEPS (K_DIM / GBK)        // 16
#define NSTAGE 4
#define ROWB 64                     // smem row stride (32 bf16)
#define SA_BYTES (128 * ROWB)       // 8192
#define SB_BYTES (256 * ROWB)       // 16384
#define STAGE_BYTES (2 * SA_BYTES + 2 * SB_BYTES)   // 49152
#define OFF_AHI 0
#define OFF_ALO SA_BYTES
#define OFF_BHI (2 * SA_BYTES)
#define OFF_BLO (2 * SA_BYTES + SB_BYTES)
#define GEMM_SMEM (NSTAGE * STAGE_BYTES)            // 196608

__device__ __forceinline__ void load_stage(uint32_t sb, int stage, int kt,
                                           int mbase, int nbase, int tid) {
    const int k0 = kt * GBK;
    const uint32_t dst = sb + stage * STAGE_BYTES;
    // A arrays: 128 rows x 4 16B-units = 512 ops each; 512 threads -> 1 op
    {
        int row = tid >> 2, u = tid & 3;
        uint32_t o = row * ROWB + u * 16;
        const size_t g = (size_t)(mbase + row) * K_DIM + k0 + u * 8;
        cpa16(dst + OFF_AHI + o, g_Ahi + g);
        cpa16(dst + OFF_ALO + o, g_Alo + g);
    }
    // B arrays: 256 rows x 4 units = 1024 ops each; 2 per thread
#pragma unroll
    for (int j = 0; j < 2; ++j) {
        int unit = tid + j * 512;
        int row = unit >> 2, u = unit & 3;
        uint32_t o = row * ROWB + u * 16;
        const size_t g = (size_t)(nbase + row) * K_DIM + k0 + u * 8;
        cpa16(dst + OFF_BHI + o, g_Bhi + g);
        cpa16(dst + OFF_BLO + o, g_Blo + g);
    }
    cpa_commit();
}

__global__ __launch_bounds__(512) void indgru_gemm_mma() {
    extern __shared__ __align__(128) char smem[];
    const uint32_t sb = smem_u32(smem);
    const int tid = threadIdx.x;
    const int wid = tid >> 5;
    const int lid = tid & 31;
    const int mbase = blockIdx.x * GBM;
    const int nbase = blockIdx.y * GBN;

    const int m_warp = (wid >> 3) * 64;    // 0 or 64
    const int n_warp = (wid & 7) * 32;     // 0..224

    // ldmatrix per-lane address components (row stride ROWB)
    const int rowA = m_warp + (lid & 7) + ((lid >> 3) & 1) * 8;
    const uint32_t aBase = rowA * ROWB + ((lid >> 4) & 1) * 16;
    const int rowBm = n_warp + (lid & 7) + ((lid >> 4) & 1) * 8;
    const uint32_t bBase = rowBm * ROWB + ((lid >> 3) & 1) * 16;

    float c[4][4][4];
#pragma unroll
    for (int i = 0; i < 4; ++i)
#pragma unroll
        for (int j = 0; j < 4; ++j)
#pragma unroll
            for (int q = 0; q < 4; ++q) c[i][j][q] = 0.f;

    load_stage(sb, 0, 0, mbase, nbase, tid);
    load_stage(sb, 1, 1, mbase, nbase, tid);
    load_stage(sb, 2, 2, mbase, nbase, tid);

    for (int kt = 0; kt < NSTEPS; ++kt) {
        const int stage = kt & (NSTAGE - 1);
        cpa_wait<2>();
        __syncthreads();   // stage kt ready for all; stage kt-1 fully consumed

        if (kt + 3 < NSTEPS)
            load_stage(sb, (kt + 3) & (NSTAGE - 1), kt + 3, mbase, nbase, tid);

        const uint32_t st = sb + stage * STAGE_BYTES;
#pragma unroll
        for (int ks = 0; ks < 2; ++ks) {
            uint32_t Ah[4][4], Al[4][4], Bh[2][4], Bl[2][4];
#pragma unroll
            for (int mf = 0; mf < 4; ++mf) {
                uint32_t ao = aBase + mf * (16 * ROWB) + ks * 32;
                ldm4(Ah[mf], st + OFF_AHI + ao);
                ldm4(Al[mf], st + OFF_ALO + ao);
            }
#pragma unroll
            for (int nfp = 0; nfp < 2; ++nfp) {
                uint32_t bo = bBase + nfp * (16 * ROWB) + ks * 32;
                ldm4(Bh[nfp], st + OFF_BHI + bo);
                ldm4(Bl[nfp], st + OFF_BLO + bo);
            }
#pragma unroll
            for (int mf = 0; mf < 4; ++mf) {
#pragma unroll
                for (int nfp = 0; nfp < 2; ++nfp) {
#pragma unroll
                    for (int hf = 0; hf < 2; ++hf) {
                        const int nf = nfp * 2 + hf;
                        mma_bf16(c[mf][nf], Ah[mf], &Bh[nfp][hf * 2]);
                        mma_bf16(c[mf][nf], Ah[mf], &Bl[nfp][hf * 2]);
                        mma_bf16(c[mf][nf], Al[mf], &Bh[nfp][hf * 2]);
                    }
                }
            }
        }
    }

    // epilogue: c[mf][nf] -> g_gx
    const int g = lid >> 2, t4 = lid & 3;
#pragma unroll
    for (int mf = 0; mf < 4; ++mf) {
        const int m0 = mbase + m_warp + mf * 16 + g;
        float* r0 = g_gx + (size_t)m0 * N_DIM + nbase + n_warp;
        float* r1 = r0 + (size_t)8 * N_DIM;
#pragma unroll
        for (int nf = 0; nf < 4; ++nf) {
            const int nc = nf * 8 + 2 * t4;
            *reinterpret_cast<float2*>(r0 + nc) =
                make_float2(c[mf][nf][0], c[mf][nf][1]);
            *reinterpret_cast<float2*>(r1 + nc) =
                make_float2(c[mf][nf][2], c[mf][nf][3]);
        }
    }
}

// ---------------------------------------------------------------------------
// Scan: one thread per (b, h); diagonal recurrence over T=512 steps.
// Depth-16 prefetch ring; log2e folding done off the dependent chain at
// prefetch time; raw ex2/rcp MUFU ops; no clamps (saturating arithmetic safe).
// ---------------------------------------------------------------------------
#define C_NL2E (-1.44269504088896f)   // -log2 e
#define C_2L2E (2.88539008177793f)    // 2 log2 e

__global__ __launch_bounds__(128)
void indgru_scan(const float* __restrict__ h0, const float* __restrict__ w_hh,
                 float* __restrict__ out) {
    const int idx = blockIdx.x * 128 + threadIdx.x;   // 0..16383
    const int b = idx >> 9;
    const int h = idx & (H_DIM - 1);

    const float nwr = C_NL2E * w_hh[h];
    const float nwz = C_NL2E * w_hh[H_DIM + h];
    const float wn2 = C_2L2E * w_hh[2 * H_DIM + h];

    float hv = h0[idx];

    const float* gbase = g_gx + (size_t)b * N_DIM + h;
    const int TSTRIDE = B_DIM * N_DIM;                 // 49152

    const int PF = 16;
    float bgr[PF], bgz[PF], bgn[PF];   // pre-scaled: -l2e*gr, -l2e*gz, 2l2e*gn
#pragma unroll
    for (int i = 0; i < PF; ++i) {
        const float* gp = gbase + (size_t)i * TSTRIDE;
        bgr[i] = C_NL2E * __ldcs(gp);
        bgz[i] = C_NL2E * __ldcs(gp + H_DIM);
        bgn[i] = C_2L2E * __ldcs(gp + 2 * H_DIM);
    }

    float* op = out + idx;

#pragma unroll 16
    for (int t = 0; t < T_DIM; ++t) {
        const int s = t & (PF - 1);
        const float ngr = bgr[s], ngz = bgz[s], gn2 = bgn[s];

        const int tp = t + PF;
        if (tp < T_DIM) {
            const float* gp = gbase + (size_t)tp * TSTRIDE;
            bgr[s] = C_NL2E * __ldcs(gp);
            bgz[s] = C_NL2E * __ldcs(gp + H_DIM);
            bgn[s] = C_2L2E * __ldcs(gp + 2 * H_DIM);
        }

        // r = sigmoid(gr + wr*hv) = 1/(1 + 2^(nwr*hv + ngr))
        const float er = ex2f(fmaf(nwr, hv, ngr));
        const float r  = rcpf(1.f + er);
        const float ez = ex2f(fmaf(nwz, hv, ngz));
        const float z  = rcpf(1.f + ez);
        // n = tanh(gn + r*wn*hv) = 1 - 2/(2^(2l2e*(gn + r*wn*hv)) + 1)
        const float wnh2 = wn2 * hv;
        const float e2 = ex2f(fmaf(r, wnh2, gn2));
        const float n  = fmaf(-2.f, rcpf(1.f + e2), 1.f);
        hv = fmaf(z, hv - n, n);

        __stcs(op + (size_t)t * (B_DIM * H_DIM), hv);
    }
    __stcs(op + (size_t)T_DIM * (B_DIM * H_DIM), hv);
}

// ---------------------------------------------------------------------------
extern "C" void kernel_launch(void* const* d_in, const int* in_sizes, int n_in,
                              void* d_out, int out_size) {
    const float* x    = (const float*)d_in[0];   // (T, B, I)
    const float* h0   = (const float*)d_in[1];   // (B, H)
    const float* W_ih = (const float*)d_in[2];   // (3H, I)
    const float* w_hh = (const float*)d_in[3];   // (3, H)
    float* out = (float*)d_out;

    convert_split_A<<<2048, 256>>>((const float4*)x);
    convert_split_B<<<768, 256>>>((const float4*)W_ih);

    cudaFuncSetAttribute(indgru_gemm_mma,
                         cudaFuncAttributeMaxDynamicSharedMemorySize, GEMM_SMEM);
    dim3 grid(M_DIM / GBM, N_DIM / GBN);   // 128 x 6
    indgru_gemm_mma<<<grid, 512, GEMM_SMEM>>>();

    indgru_scan<<<(B_DIM * H_DIM) / 128, 128>>>(h0, w_hh, out);
}

// round 5
// speedup vs baseline: 1.9564x; 1.9564x over previous
#include <cuda_runtime.h>
#include <cuda_bf16.h>
#include <cstdint>

// Problem dims (fixed per reference)
#define T_DIM 512
#define B_DIM 32
#define I_DIM 512
#define H_DIM 512
#define M_DIM (T_DIM * B_DIM)   // 16384
#define N_DIM (3 * H_DIM)       // 1536
#define K_DIM I_DIM             // 512

// ---------------------------------------------------------------------------
// Device scratch (no allocs allowed)
// ---------------------------------------------------------------------------
__device__ float         g_gx[(size_t)M_DIM * N_DIM];          // 100 MB
__device__ __nv_bfloat16 g_Ahi[(size_t)M_DIM * K_DIM];         // 16 MB
__device__ __nv_bfloat16 g_Alo[(size_t)M_DIM * K_DIM];         // 16 MB
__device__ __nv_bfloat16 g_Bhi[(size_t)N_DIM * K_DIM];         // 1.5 MB
__device__ __nv_bfloat16 g_Blo[(size_t)N_DIM * K_DIM];         // 1.5 MB

// ---------------------------------------------------------------------------
// PTX helpers (baseline-PTX features only: cp.async, ldmatrix, mma.sync)
// ---------------------------------------------------------------------------
__device__ __forceinline__ uint32_t smem_u32(const void* p) {
    uint32_t a;
    asm("{ .reg .u64 t; cvta.to.shared.u64 t, %1; cvt.u32.u64 %0, t; }"
        : "=r"(a) : "l"(p));
    return a;
}
__device__ __forceinline__ void cpa16(uint32_t dst, const void* src) {
    asm volatile("cp.async.cg.shared.global [%0], [%1], 16;"
                 :: "r"(dst), "l"(src));
}
__device__ __forceinline__ void cpa_commit() {
    asm volatile("cp.async.commit_group;" ::: "memory");
}
template <int N>
__device__ __forceinline__ void cpa_wait() {
    asm volatile("cp.async.wait_group %0;" :: "n"(N) : "memory");
}
__device__ __forceinline__ void ldm4(uint32_t* r, uint32_t addr) {
    asm volatile("ldmatrix.sync.aligned.m8n8.x4.shared.b16 {%0,%1,%2,%3}, [%4];"
                 : "=r"(r[0]), "=r"(r[1]), "=r"(r[2]), "=r"(r[3]) : "r"(addr));
}
__device__ __forceinline__ void mma_bf16(float* c, const uint32_t* a,
                                         const uint32_t* b) {
    asm volatile(
        "mma.sync.aligned.m16n8k16.row.col.f32.bf16.bf16.f32 "
        "{%0,%1,%2,%3}, {%4,%5,%6,%7}, {%8,%9}, {%0,%1,%2,%3};"
        : "+f"(c[0]), "+f"(c[1]), "+f"(c[2]), "+f"(c[3])
        : "r"(a[0]), "r"(a[1]), "r"(a[2]), "r"(a[3]), "r"(b[0]), "r"(b[1]));
}
__device__ __forceinline__ float ex2f(float x) {
    float y;
    asm("ex2.approx.f32 %0, %1;" : "=f"(y) : "f"(x));
    return y;
}
__device__ __forceinline__ float rcpf(float x) {
    float y;
    asm("rcp.approx.f32 %0, %1;" : "=f"(y) : "f"(x));
    return y;
}

// ---------------------------------------------------------------------------
// Split conversion: v -> bf16 hi + bf16 lo (residual)
// ---------------------------------------------------------------------------
__device__ __forceinline__ unsigned short f2b_split(float v, unsigned short& lo_out) {
    __nv_bfloat16 h = __float2bfloat16(v);
    float r = v - __bfloat162float(h);
    __nv_bfloat16 l = __float2bfloat16(r);
    lo_out = *reinterpret_cast<unsigned short*>(&l);
    return *reinterpret_cast<unsigned short*>(&h);
}

__global__ void convert_split_A(const float4* __restrict__ src) {
    ushort4* hi = reinterpret_cast<ushort4*>(g_Ahi);
    ushort4* lo = reinterpret_cast<ushort4*>(g_Alo);
    const int n4 = (M_DIM * K_DIM) / 4;
    const int stride = gridDim.x * blockDim.x;
    for (int i = blockIdx.x * blockDim.x + threadIdx.x; i < n4; i += stride) {
        float4 v = __ldcs(src + i);
        ushort4 h, l;
        h.x = f2b_split(v.x, l.x);
        h.y = f2b_split(v.y, l.y);
        h.z = f2b_split(v.z, l.z);
        h.w = f2b_split(v.w, l.w);
        hi[i] = h; lo[i] = l;
    }
}
__global__ void convert_split_B(const float4* __restrict__ src) {
    ushort4* hi = reinterpret_cast<ushort4*>(g_Bhi);
    ushort4* lo = reinterpret_cast<ushort4*>(g_Blo);
    const int n4 = (N_DIM * K_DIM) / 4;
    const int stride = gridDim.x * blockDim.x;
    for (int i = blockIdx.x * blockDim.x + threadIdx.x; i < n4; i += stride) {
        float4 v = __ldcs(src + i);
        ushort4 h, l;
        h.x = f2b_split(v.x, l.x);
        h.y = f2b_split(v.y, l.y);
        h.z = f2b_split(v.z, l.z);
        h.w = f2b_split(v.w, l.w);
        hi[i] = h; lo[i] = l;
    }
}

// ---------------------------------------------------------------------------
// HMMA GEMM: gx[m, n] = x[m, :] . W[n, :] via 3-pass bf16 split (mma.sync)
// CTA 128x256, 512 threads (16 warps, 2x8, warp tile 64x32), BK=32,
// 4-stage cp.async ring, one __syncthreads per stage.
// Smem rows 64 B with XOR swizzle u' = u ^ ((row>>1)&3) on 16B units
// -> ldmatrix 8-row phases tile all 8 bank groups (conflict-free).
// ---------------------------------------------------------------------------
#define GBM 128
#define GBN 256
#define GBK 32
#define NSTEPS (K_DIM / GBK)        // 16
#define NSTAGE 4
#define ROWB 64                     // smem row stride (32 bf16)
#define SA_BYTES (128 * ROWB)       // 8192
#define SB_BYTES (256 * ROWB)       // 16384
#define STAGE_BYTES (2 * SA_BYTES + 2 * SB_BYTES)   // 49152
#define OFF_AHI 0
#define OFF_ALO SA_BYTES
#define OFF_BHI (2 * SA_BYTES)
#define OFF_BLO (2 * SA_BYTES + SB_BYTES)
#define GEMM_SMEM (NSTAGE * STAGE_BYTES)            // 196608

__device__ __forceinline__ uint32_t swz_off(int row, int u) {
    return (uint32_t)(row * ROWB + ((u ^ ((row >> 1) & 3)) << 4));
}

__device__ __forceinline__ void load_stage(uint32_t sb, int stage, int kt,
                                           int mbase, int nbase, int tid) {
    const int k0 = kt * GBK;
    const uint32_t dst = sb + stage * STAGE_BYTES;
    // A arrays: 128 rows x 4 16B-units = 512 ops each; 512 threads -> 1 op
    {
        int row = tid >> 2, u = tid & 3;
        uint32_t o = swz_off(row, u);
        const size_t g = (size_t)(mbase + row) * K_DIM + k0 + u * 8;
        cpa16(dst + OFF_AHI + o, g_Ahi + g);
        cpa16(dst + OFF_ALO + o, g_Alo + g);
    }
    // B arrays: 256 rows x 4 units = 1024 ops each; 2 per thread
#pragma unroll
    for (int j = 0; j < 2; ++j) {
        int unit = tid + j * 512;
        int row = unit >> 2, u = unit & 3;
        uint32_t o = swz_off(row, u);
        const size_t g = (size_t)(nbase + row) * K_DIM + k0 + u * 8;
        cpa16(dst + OFF_BHI + o, g_Bhi + g);
        cpa16(dst + OFF_BLO + o, g_Blo + g);
    }
    cpa_commit();
}

__global__ __launch_bounds__(512) void indgru_gemm_mma() {
    extern __shared__ __align__(128) char smem[];
    const uint32_t sb = smem_u32(smem);
    const int tid = threadIdx.x;
    const int wid = tid >> 5;
    const int lid = tid & 31;
    const int mbase = blockIdx.x * GBM;
    const int nbase = blockIdx.y * GBN;

    const int m_warp = (wid >> 3) * 64;    // 0 or 64
    const int n_warp = (wid & 7) * 32;     // 0..224

    // ldmatrix per-lane row + unit components (swizzled at use)
    const int rowA = m_warp + (lid & 7) + ((lid >> 3) & 1) * 8;
    const int uA = (lid >> 4) & 1;               // + ks*2
    const int rowBm = n_warp + (lid & 7) + ((lid >> 4) & 1) * 8;
    const int uB = (lid >> 3) & 1;               // + ks*2

    float c[4][4][4];
#pragma unroll
    for (int i = 0; i < 4; ++i)
#pragma unroll
        for (int j = 0; j < 4; ++j)
#pragma unroll
            for (int q = 0; q < 4; ++q) c[i][j][q] = 0.f;

    load_stage(sb, 0, 0, mbase, nbase, tid);
    load_stage(sb, 1, 1, mbase, nbase, tid);
    load_stage(sb, 2, 2, mbase, nbase, tid);

    for (int kt = 0; kt < NSTEPS; ++kt) {
        const int stage = kt & (NSTAGE - 1);
        cpa_wait<2>();
        __syncthreads();   // stage kt ready for all; stage kt-1 fully consumed

        if (kt + 3 < NSTEPS)
            load_stage(sb, (kt + 3) & (NSTAGE - 1), kt + 3, mbase, nbase, tid);

        const uint32_t st = sb + stage * STAGE_BYTES;
#pragma unroll
        for (int ks = 0; ks < 2; ++ks) {
            uint32_t Ah[4][4], Al[4][4], Bh[2][4], Bl[2][4];
#pragma unroll
            for (int mf = 0; mf < 4; ++mf) {
                uint32_t ao = swz_off(rowA + mf * 16, uA + ks * 2);
                ldm4(Ah[mf], st + OFF_AHI + ao);
                ldm4(Al[mf], st + OFF_ALO + ao);
            }
#pragma unroll
            for (int nfp = 0; nfp < 2; ++nfp) {
                uint32_t bo = swz_off(rowBm + nfp * 16, uB + ks * 2);
                ldm4(Bh[nfp], st + OFF_BHI + bo);
                ldm4(Bl[nfp], st + OFF_BLO + bo);
            }
#pragma unroll
            for (int mf = 0; mf < 4; ++mf) {
#pragma unroll
                for (int nfp = 0; nfp < 2; ++nfp) {
#pragma unroll
                    for (int hf = 0; hf < 2; ++hf) {
                        const int nf = nfp * 2 + hf;
                        mma_bf16(c[mf][nf], Ah[mf], &Bh[nfp][hf * 2]);
                        mma_bf16(c[mf][nf], Ah[mf], &Bl[nfp][hf * 2]);
                        mma_bf16(c[mf][nf], Al[mf], &Bh[nfp][hf * 2]);
                    }
                }
            }
        }
    }

    // epilogue: c[mf][nf] -> g_gx
    const int g = lid >> 2, t4 = lid & 3;
#pragma unroll
    for (int mf = 0; mf < 4; ++mf) {
        const int m0 = mbase + m_warp + mf * 16 + g;
        float* r0 = g_gx + (size_t)m0 * N_DIM + nbase + n_warp;
        float* r1 = r0 + (size_t)8 * N_DIM;
#pragma unroll
        for (int nf = 0; nf < 4; ++nf) {
            const int nc = nf * 8 + 2 * t4;
            *reinterpret_cast<float2*>(r0 + nc) =
                make_float2(c[mf][nf][0], c[mf][nf][1]);
            *reinterpret_cast<float2*>(r1 + nc) =
                make_float2(c[mf][nf][2], c[mf][nf][3]);
        }
    }
}

// ---------------------------------------------------------------------------
// Scan: 2 independent (b, h) items per thread (ILP interleaving of the two
// ~100-cycle dependent chains). Depth-8 RAW prefetch ring (loads stay raw in
// the ring; constant folding happens at consume time, off the load path).
// ---------------------------------------------------------------------------
#define C_NL2E (-1.44269504088896f)   // -log2 e
#define C_2L2E (2.88539008177793f)    // 2 log2 e
#define SCAN_PF 8

struct ScanItem {
    float hv, nwr, nwz, wn;
    const float* gbase;
    float* op;
    float bgr[SCAN_PF], bgz[SCAN_PF], bgn[SCAN_PF];
};

__device__ __forceinline__ void scan_init(ScanItem& it, int idx,
                                          const float* __restrict__ h0,
                                          const float* __restrict__ w_hh,
                                          float* __restrict__ out) {
    const int b = idx >> 9;
    const int h = idx & (H_DIM - 1);
    it.nwr = C_NL2E * w_hh[h];
    it.nwz = C_NL2E * w_hh[H_DIM + h];
    it.wn  = w_hh[2 * H_DIM + h];
    it.hv  = h0[idx];
    it.gbase = g_gx + (size_t)b * N_DIM + h;
    it.op = out + idx;
    const int TSTRIDE = B_DIM * N_DIM;
#pragma unroll
    for (int i = 0; i < SCAN_PF; ++i) {
        const float* gp = it.gbase + (size_t)i * TSTRIDE;
        it.bgr[i] = __ldcs(gp);
        it.bgz[i] = __ldcs(gp + H_DIM);
        it.bgn[i] = __ldcs(gp + 2 * H_DIM);
    }
}

__device__ __forceinline__ void scan_step(ScanItem& it, int t, int s) {
    const float gr = it.bgr[s], gz = it.bgz[s], gn = it.bgn[s];
    const int tp = t + SCAN_PF;
    if (tp < T_DIM) {
        const float* gp = it.gbase + (size_t)tp * (B_DIM * N_DIM);
        it.bgr[s] = __ldcs(gp);
        it.bgz[s] = __ldcs(gp + H_DIM);
        it.bgn[s] = __ldcs(gp + 2 * H_DIM);
    }
    const float hv = it.hv;
    // r = sigmoid(gr + wr*h) = 1/(1 + 2^(-l2e*(gr + wr*h)))
    const float er = ex2f(C_NL2E * fmaf(-it.nwr * (1.f / C_NL2E), 0.f, 0.f) +
                          fmaf(it.nwr, hv, C_NL2E * gr));
    const float r  = rcpf(1.f + er);
    const float ez = ex2f(fmaf(it.nwz, hv, C_NL2E * gz));
    const float z  = rcpf(1.f + ez);
    const float wnh = it.wn * hv;                      // off-chain vs r
    const float e2 = ex2f(C_2L2E * fmaf(r, wnh, gn));
    const float n  = fmaf(-2.f, rcpf(1.f + e2), 1.f);
    it.hv = fmaf(z, hv - n, n);
    __stcs(it.op + (size_t)t * (B_DIM * H_DIM), it.hv);
}

__global__ __launch_bounds__(128)
void indgru_scan(const float* __restrict__ h0, const float* __restrict__ w_hh,
                 float* __restrict__ out) {
    const int gid = blockIdx.x * 128 + threadIdx.x;   // 0..8191
    ScanItem a, b;
    scan_init(a, gid, h0, w_hh, out);
    scan_init(b, gid + 8192, h0, w_hh, out);

#pragma unroll 8
    for (int t = 0; t < T_DIM; ++t) {
        const int s = t & (SCAN_PF - 1);
        scan_step(a, t, s);
        scan_step(b, t, s);
    }
    __stcs(a.op + (size_t)T_DIM * (B_DIM * H_DIM), a.hv);
    __stcs(b.op + (size_t)T_DIM * (B_DIM * H_DIM), b.hv);
}

// ---------------------------------------------------------------------------
extern "C" void kernel_launch(void* const* d_in, const int* in_sizes, int n_in,
                              void* d_out, int out_size) {
    const float* x    = (const float*)d_in[0];   // (T, B, I)
    const float* h0   = (const float*)d_in[1];   // (B, H)
    const float* W_ih = (const float*)d_in[2];   // (3H, I)
    const float* w_hh = (const float*)d_in[3];   // (3, H)
    float* out = (float*)d_out;

    convert_split_A<<<2048, 256>>>((const float4*)x);
    convert_split_B<<<768, 256>>>((const float4*)W_ih);

    cudaFuncSetAttribute(indgru_gemm_mma,
                         cudaFuncAttributeMaxDynamicSharedMemorySize, GEMM_SMEM);
    dim3 grid(M_DIM / GBM, N_DIM / GBN);   // 128 x 6
    indgru_gemm_mma<<<grid, 512, GEMM_SMEM>>>();

    indgru_scan<<<(B_DIM * H_DIM) / (2 * 128), 128>>>(h0, w_hh, out);
}

// round 8
// speedup vs baseline: 2.5936x; 1.3257x over previous
#include <cuda_runtime.h>
#include <cuda_fp16.h>
#include <cstdint>

// Problem dims (fixed per reference)
#define T_DIM 512
#define B_DIM 32
#define I_DIM 512
#define H_DIM 512
#define M_DIM (T_DIM * B_DIM)   // 16384
#define N_DIM (3 * H_DIM)       // 1536
#define K_DIM I_DIM             // 512

// ---------------------------------------------------------------------------
// Device scratch (no allocs allowed)
// ---------------------------------------------------------------------------
__device__ float  g_gx[(size_t)M_DIM * N_DIM];      // 100 MB
__device__ __half g_A  [(size_t)M_DIM * K_DIM];     // 16 MB (fp16, unsplit)
__device__ __half g_Bhi[(size_t)N_DIM * K_DIM];     // 1.5 MB
__device__ __half g_Blo[(size_t)N_DIM * K_DIM];     // 1.5 MB

// ---------------------------------------------------------------------------
// PTX helpers (baseline-PTX features only: cp.async, ldmatrix, mma.sync)
// ---------------------------------------------------------------------------
__device__ __forceinline__ uint32_t smem_u32(const void* p) {
    uint32_t a;
    asm("{ .reg .u64 t; cvta.to.shared.u64 t, %1; cvt.u32.u64 %0, t; }"
        : "=r"(a) : "l"(p));
    return a;
}
__device__ __forceinline__ void cpa16(uint32_t dst, const void* src) {
    asm volatile("cp.async.cg.shared.global [%0], [%1], 16;"
                 :: "r"(dst), "l"(src));
}
__device__ __forceinline__ void cpa_commit() {
    asm volatile("cp.async.commit_group;" ::: "memory");
}
template <int N>
__device__ __forceinline__ void cpa_wait() {
    asm volatile("cp.async.wait_group %0;" :: "n"(N) : "memory");
}
__device__ __forceinline__ void ldm4(uint32_t* r, uint32_t addr) {
    asm volatile("ldmatrix.sync.aligned.m8n8.x4.shared.b16 {%0,%1,%2,%3}, [%4];"
                 : "=r"(r[0]), "=r"(r[1]), "=r"(r[2]), "=r"(r[3]) : "r"(addr));
}
__device__ __forceinline__ void mma_f16(float* c, const uint32_t* a,
                                        const uint32_t* b) {
    asm volatile(
        "mma.sync.aligned.m16n8k16.row.col.f32.f16.f16.f32 "
        "{%0,%1,%2,%3}, {%4,%5,%6,%7}, {%8,%9}, {%0,%1,%2,%3};"
        : "+f"(c[0]), "+f"(c[1]), "+f"(c[2]), "+f"(c[3])
        : "r"(a[0]), "r"(a[1]), "r"(a[2]), "r"(a[3]), "r"(b[0]), "r"(b[1]));
}
__device__ __forceinline__ float ex2f(float x) {
    float y;
    asm("ex2.approx.f32 %0, %1;" : "=f"(y) : "f"(x));
    return y;
}
__device__ __forceinline__ float rcpf(float x) {
    float y;
    asm("rcp.approx.f32 %0, %1;" : "=f"(y) : "f"(x));
    return y;
}

// ---------------------------------------------------------------------------
// Converts
// ---------------------------------------------------------------------------
__global__ void convert_A(const float4* __restrict__ src) {
    ushort4* dst = reinterpret_cast<ushort4*>(g_A);
    const int n4 = (M_DIM * K_DIM) / 4;
    const int stride = gridDim.x * blockDim.x;
    for (int i = blockIdx.x * blockDim.x + threadIdx.x; i < n4; i += stride) {
        float4 v = __ldcs(src + i);
        ushort4 o;
        __half a = __float2half_rn(v.x), b = __float2half_rn(v.y);
        __half c = __float2half_rn(v.z), d = __float2half_rn(v.w);
        o.x = *(unsigned short*)&a; o.y = *(unsigned short*)&b;
        o.z = *(unsigned short*)&c; o.w = *(unsigned short*)&d;
        dst[i] = o;
    }
}
__device__ __forceinline__ unsigned short f2h_split(float v, unsigned short& lo) {
    __half h = __float2half_rn(v);
    __half l = __float2half_rn(v - __half2float(h));
    lo = *(unsigned short*)&l;
    return *(unsigned short*)&h;
}
__global__ void convert_B(const float4* __restrict__ src) {
    ushort4* hi = reinterpret_cast<ushort4*>(g_Bhi);
    ushort4* lo = reinterpret_cast<ushort4*>(g_Blo);
    const int n4 = (N_DIM * K_DIM) / 4;
    const int stride = gridDim.x * blockDim.x;
    for (int i = blockIdx.x * blockDim.x + threadIdx.x; i < n4; i += stride) {
        float4 v = __ldcs(src + i);
        ushort4 h, l;
        h.x = f2h_split(v.x, l.x);
        h.y = f2h_split(v.y, l.y);
        h.z = f2h_split(v.z, l.z);
        h.w = f2h_split(v.w, l.w);
        hi[i] = h; lo[i] = l;
    }
}

// ---------------------------------------------------------------------------
// HMMA GEMM: gx = A . B^T with A fp16 (unsplit), B = B_hi + B_lo (fp16 split)
// 2 MMA passes per fragment. CTA 128x256, 512 threads (16 warps, warp 64x32),
// BK=32, 4-stage cp.async ring, one __syncthreads per stage.
// Smem rows 64 B, XOR swizzle u' = u ^ ((row>>1)&3) -> conflict-free ldmatrix.
// ---------------------------------------------------------------------------
#define GBM 128
#define GBN 256
#define GBK 32
#define NSTEPS (K_DIM / GBK)        // 16
#define NSTAGE 4
#define ROWB 64                     // smem row stride (32 fp16)
#define SA_BYTES (128 * ROWB)       // 8192
#define SB_BYTES (256 * ROWB)       // 16384
#define STAGE_BYTES (SA_BYTES + 2 * SB_BYTES)       // 40960
#define OFF_A   0
#define OFF_BHI SA_BYTES
#define OFF_BLO (SA_BYTES + SB_BYTES)
#define GEMM_SMEM (NSTAGE * STAGE_BYTES)            // 163840

__device__ __forceinline__ uint32_t swz_off(int row, int u) {
    return (uint32_t)(row * ROWB + ((u ^ ((row >> 1) & 3)) << 4));
}

__device__ __forceinline__ void load_stage(uint32_t sb, int stage, int kt,
                                           int mbase, int nbase, int tid) {
    const int k0 = kt * GBK;
    const uint32_t dst = sb + stage * STAGE_BYTES;
    // A: 128 rows x 4 16B-units = 512 ops; 512 threads -> 1 each
    {
        int row = tid >> 2, u = tid & 3;
        cpa16(dst + OFF_A + swz_off(row, u),
              g_A + (size_t)(mbase + row) * K_DIM + k0 + u * 8);
    }
    // B hi/lo: 256 rows x 4 units = 1024 ops each; 2 per thread per array
#pragma unroll
    for (int j = 0; j < 2; ++j) {
        int unit = tid + j * 512;
        int row = unit >> 2, u = unit & 3;
        uint32_t o = swz_off(row, u);
        const size_t g = (size_t)(nbase + row) * K_DIM + k0 + u * 8;
        cpa16(dst + OFF_BHI + o, g_Bhi + g);
        cpa16(dst + OFF_BLO + o, g_Blo + g);
    }
    cpa_commit();
}

__global__ __launch_bounds__(512) void indgru_gemm_mma() {
    extern __shared__ __align__(128) char smem[];
    const uint32_t sb = smem_u32(smem);
    const int tid = threadIdx.x;
    const int wid = tid >> 5;
    const int lid = tid & 31;
    const int mbase = blockIdx.x * GBM;
    const int nbase = blockIdx.y * GBN;

    const int m_warp = (wid >> 3) * 64;    // 0 or 64
    const int n_warp = (wid & 7) * 32;     // 0..224

    // ldmatrix per-lane row + unit components (swizzled at use)
    const int rowA = m_warp + (lid & 7) + ((lid >> 3) & 1) * 8;
    const int uA = (lid >> 4) & 1;               // + ks*2
    const int rowBm = n_warp + (lid & 7) + ((lid >> 4) & 1) * 8;
    const int uB = (lid >> 3) & 1;               // + ks*2

    float c[4][4][4];
#pragma unroll
    for (int i = 0; i < 4; ++i)
#pragma unroll
        for (int j = 0; j < 4; ++j)
#pragma unroll
            for (int q = 0; q < 4; ++q) c[i][j][q] = 0.f;

    load_stage(sb, 0, 0, mbase, nbase, tid);
    load_stage(sb, 1, 1, mbase, nbase, tid);
    load_stage(sb, 2, 2, mbase, nbase, tid);

    for (int kt = 0; kt < NSTEPS; ++kt) {
        const int stage = kt & (NSTAGE - 1);
        cpa_wait<2>();
        __syncthreads();   // stage kt ready; stage kt-1 fully consumed

        if (kt + 3 < NSTEPS)
            load_stage(sb, (kt + 3) & (NSTAGE - 1), kt + 3, mbase, nbase, tid);

        const uint32_t st = sb + stage * STAGE_BYTES;
#pragma unroll
        for (int ks = 0; ks < 2; ++ks) {
            uint32_t Ah[4][4], Bh[2][4], Bl[2][4];
#pragma unroll
            for (int mf = 0; mf < 4; ++mf)
                ldm4(Ah[mf], st + OFF_A + swz_off(rowA + mf * 16, uA + ks * 2));
#pragma unroll
            for (int nfp = 0; nfp < 2; ++nfp) {
                uint32_t bo = swz_off(rowBm + nfp * 16, uB + ks * 2);
                ldm4(Bh[nfp], st + OFF_BHI + bo);
                ldm4(Bl[nfp], st + OFF_BLO + bo);
            }
#pragma unroll
            for (int mf = 0; mf < 4; ++mf) {
#pragma unroll
                for (int nfp = 0; nfp < 2; ++nfp) {
#pragma unroll
                    for (int hf = 0; hf < 2; ++hf) {
                        const int nf = nfp * 2 + hf;
                        mma_f16(c[mf][nf], Ah[mf], &Bh[nfp][hf * 2]);
                        mma_f16(c[mf][nf], Ah[mf], &Bl[nfp][hf * 2]);
                    }
                }
            }
        }
    }

    // epilogue: c[mf][nf] -> g_gx
    const int g = lid >> 2, t4 = lid & 3;
#pragma unroll
    for (int mf = 0; mf < 4; ++mf) {
        const int m0 = mbase + m_warp + mf * 16 + g;
        float* r0 = g_gx + (size_t)m0 * N_DIM + nbase + n_warp;
        float* r1 = r0 + (size_t)8 * N_DIM;
#pragma unroll
        for (int nf = 0; nf < 4; ++nf) {
            const int nc = nf * 8 + 2 * t4;
            *reinterpret_cast<float2*>(r0 + nc) =
                make_float2(c[mf][nf][0], c[mf][nf][1]);
            *reinterpret_cast<float2*>(r1 + nc) =
                make_float2(c[mf][nf][2], c[mf][nf][3]);
        }
    }
}

// ---------------------------------------------------------------------------
// Scan: one thread per (b, h); 16384 threads, 256 blocks x 64 threads.
// Depth-8 RAW prefetch ring (raw loads in ring; constant folding at consume
// time, off the load path). Folded ex2/rcp gate math, no clamps.
// ---------------------------------------------------------------------------
#define C_NL2E (-1.44269504088896f)   // -log2 e
#define C_2L2E (2.88539008177793f)    // 2 log2 e
#define SCAN_PF 8

__global__ __launch_bounds__(64)
void indgru_scan(const float* __restrict__ h0, const float* __restrict__ w_hh,
                 float* __restrict__ out) {
    const int idx = blockIdx.x * 64 + threadIdx.x;    // 0..16383
    const int b = idx >> 9;
    const int h = idx & (H_DIM - 1);

    const float nwr = C_NL2E * w_hh[h];
    const float nwz = C_NL2E * w_hh[H_DIM + h];
    const float wn2 = C_2L2E * w_hh[2 * H_DIM + h];

    float hv = h0[idx];

    const float* gbase = g_gx + (size_t)b * N_DIM + h;
    const int TSTRIDE = B_DIM * N_DIM;                // 49152

    float bgr[SCAN_PF], bgz[SCAN_PF], bgn[SCAN_PF];   // raw loads
#pragma unroll
    for (int i = 0; i < SCAN_PF; ++i) {
        const float* gp = gbase + (size_t)i * TSTRIDE;
        bgr[i] = __ldcs(gp);
        bgz[i] = __ldcs(gp + H_DIM);
        bgn[i] = __ldcs(gp + 2 * H_DIM);
    }

    float* op = out + idx;

#pragma unroll 8
    for (int t = 0; t < T_DIM; ++t) {
        const int s = t & (SCAN_PF - 1);
        const float gr = bgr[s], gz = bgz[s], gn = bgn[s];

        const int tp = t + SCAN_PF;
        if (tp < T_DIM) {
            const float* gp = gbase + (size_t)tp * TSTRIDE;
            bgr[s] = __ldcs(gp);
            bgz[s] = __ldcs(gp + H_DIM);
            bgn[s] = __ldcs(gp + 2 * H_DIM);
        }

        // scaled gate biases: off the dependent chain (gr/gz/gn ready long ago)
        const float ngr = C_NL2E * gr;
        const float ngz = C_NL2E * gz;
        const float gn2 = C_2L2E * gn;

        // r = sigmoid(gr + wr*h) = 1/(1 + 2^(nwr*h + ngr))
        const float er = ex2f(fmaf(nwr, hv, ngr));
        const float r  = rcpf(1.f + er);
        const float ez = ex2f(fmaf(nwz, hv, ngz));
        const float z  = rcpf(1.f + ez);
        // n = tanh(gn + r*wn*h) = 1 - 2/(2^(2l2e*(gn + r*wn*h)) + 1)
        const float wnh2 = wn2 * hv;                  // off-chain vs r
        const float e2 = ex2f(fmaf(r, wnh2, gn2));
        const float n  = fmaf(-2.f, rcpf(1.f + e2), 1.f);
        hv = fmaf(z, hv - n, n);

        __stcs(op + (size_t)t * (B_DIM * H_DIM), hv);
    }
    __stcs(op + (size_t)T_DIM * (B_DIM * H_DIM), hv);
}

// ---------------------------------------------------------------------------
extern "C" void kernel_launch(void* const* d_in, const int* in_sizes, int n_in,
                              void* d_out, int out_size) {
    const float* x    = (const float*)d_in[0];   // (T, B, I)
    const float* h0   = (const float*)d_in[1];   // (B, H)
    const float* W_ih = (const float*)d_in[2];   // (3H, I)
    const float* w_hh = (const float*)d_in[3];   // (3, H)
    float* out = (float*)d_out;

    convert_A<<<1024, 256>>>((const float4*)x);
    convert_B<<<768, 256>>>((const float4*)W_ih);

    cudaFuncSetAttribute(indgru_gemm_mma,
                         cudaFuncAttributeMaxDynamicSharedMemorySize, GEMM_SMEM);
    dim3 grid(M_DIM / GBM, N_DIM / GBN);   // 128 x 6
    indgru_gemm_mma<<<grid, 512, GEMM_SMEM>>>();

    indgru_scan<<<(B_DIM * H_DIM) / 64, 64>>>(h0, w_hh, out);
}

// round 9
// speedup vs baseline: 3.7021x; 1.4274x over previous
#include <cuda_runtime.h>
#include <cuda_fp16.h>
#include <cstdint>

// Problem dims (fixed per reference)
#define T_DIM 512
#define B_DIM 32
#define I_DIM 512
#define H_DIM 512
#define M_DIM (T_DIM * B_DIM)   // 16384
#define N_DIM (3 * H_DIM)       // 1536
#define K_DIM I_DIM             // 512

// ---------------------------------------------------------------------------
// Device scratch (no allocs allowed)
// ---------------------------------------------------------------------------
__device__ float  g_gx[(size_t)M_DIM * N_DIM];      // 100 MB
__device__ __half g_A [(size_t)M_DIM * K_DIM];      // 16 MB
__device__ __half g_B [(size_t)N_DIM * K_DIM];      // 1.5 MB

// ---------------------------------------------------------------------------
// PTX helpers (baseline-PTX features only: cp.async, ldmatrix, mma.sync)
// ---------------------------------------------------------------------------
__device__ __forceinline__ uint32_t smem_u32(const void* p) {
    uint32_t a;
    asm("{ .reg .u64 t; cvta.to.shared.u64 t, %1; cvt.u32.u64 %0, t; }"
        : "=r"(a) : "l"(p));
    return a;
}
__device__ __forceinline__ void cpa16(uint32_t dst, const void* src) {
    asm volatile("cp.async.cg.shared.global [%0], [%1], 16;"
                 :: "r"(dst), "l"(src));
}
__device__ __forceinline__ void cpa_commit() {
    asm volatile("cp.async.commit_group;" ::: "memory");
}
template <int N>
__device__ __forceinline__ void cpa_wait() {
    asm volatile("cp.async.wait_group %0;" :: "n"(N) : "memory");
}
__device__ __forceinline__ void ldm4(uint32_t* r, uint32_t addr) {
    asm volatile("ldmatrix.sync.aligned.m8n8.x4.shared.b16 {%0,%1,%2,%3}, [%4];"
                 : "=r"(r[0]), "=r"(r[1]), "=r"(r[2]), "=r"(r[3]) : "r"(addr));
}
__device__ __forceinline__ void mma_f16(float* c, const uint32_t* a,
                                        const uint32_t* b) {
    asm volatile(
        "mma.sync.aligned.m16n8k16.row.col.f32.f16.f16.f32 "
        "{%0,%1,%2,%3}, {%4,%5,%6,%7}, {%8,%9}, {%0,%1,%2,%3};"
        : "+f"(c[0]), "+f"(c[1]), "+f"(c[2]), "+f"(c[3])
        : "r"(a[0]), "r"(a[1]), "r"(a[2]), "r"(a[3]), "r"(b[0]), "r"(b[1]));
}
__device__ __forceinline__ float ex2f(float x) {
    float y;
    asm("ex2.approx.f32 %0, %1;" : "=f"(y) : "f"(x));
    return y;
}
__device__ __forceinline__ float rcpf(float x) {
    float y;
    asm("rcp.approx.f32 %0, %1;" : "=f"(y) : "f"(x));
    return y;
}

// ---------------------------------------------------------------------------
// Converts: fp32 -> fp16 stream
// ---------------------------------------------------------------------------
__device__ __forceinline__ ushort4 f4_to_h4(float4 v) {
    ushort4 o;
    __half a = __float2half_rn(v.x), b = __float2half_rn(v.y);
    __half c = __float2half_rn(v.z), d = __float2half_rn(v.w);
    o.x = *(unsigned short*)&a; o.y = *(unsigned short*)&b;
    o.z = *(unsigned short*)&c; o.w = *(unsigned short*)&d;
    return o;
}
__global__ void convert_A(const float4* __restrict__ src) {
    ushort4* dst = reinterpret_cast<ushort4*>(g_A);
    const int n4 = (M_DIM * K_DIM) / 4;
    const int stride = gridDim.x * blockDim.x;
    for (int i = blockIdx.x * blockDim.x + threadIdx.x; i < n4; i += stride)
        dst[i] = f4_to_h4(__ldcs(src + i));
}
__global__ void convert_B(const float4* __restrict__ src) {
    ushort4* dst = reinterpret_cast<ushort4*>(g_B);
    const int n4 = (N_DIM * K_DIM) / 4;
    const int stride = gridDim.x * blockDim.x;
    for (int i = blockIdx.x * blockDim.x + threadIdx.x; i < n4; i += stride)
        dst[i] = f4_to_h4(__ldcs(src + i));
}

// ---------------------------------------------------------------------------
// HMMA GEMM: gx = A . B^T, fp16 x fp16 -> fp32 accum, single pass.
// CTA 128x256, 512 threads (16 warps, warp 64x32), BK=32,
// 4-stage cp.async ring, one __syncthreads per stage.
// Smem rows 64 B, XOR swizzle u' = u ^ ((row>>1)&3) -> conflict-free ldmatrix.
// ---------------------------------------------------------------------------
#define GBM 128
#define GBN 256
#define GBK 32
#define NSTEPS (K_DIM / GBK)        // 16
#define NSTAGE 4
#define ROWB 64                     // smem row stride (32 fp16)
#define SA_BYTES (128 * ROWB)       // 8192
#define SB_BYTES (256 * ROWB)       // 16384
#define STAGE_BYTES (SA_BYTES + SB_BYTES)           // 24576
#define OFF_A 0
#define OFF_B SA_BYTES
#define GEMM_SMEM (NSTAGE * STAGE_BYTES)            // 98304

__device__ __forceinline__ uint32_t swz_off(int row, int u) {
    return (uint32_t)(row * ROWB + ((u ^ ((row >> 1) & 3)) << 4));
}

__device__ __forceinline__ void load_stage(uint32_t sb, int stage, int kt,
                                           int mbase, int nbase, int tid) {
    const int k0 = kt * GBK;
    const uint32_t dst = sb + stage * STAGE_BYTES;
    // A: 128 rows x 4 16B-units = 512 ops; 1 per thread
    {
        int row = tid >> 2, u = tid & 3;
        cpa16(dst + OFF_A + swz_off(row, u),
              g_A + (size_t)(mbase + row) * K_DIM + k0 + u * 8);
    }
    // B: 256 rows x 4 units = 1024 ops; 2 per thread
#pragma unroll
    for (int j = 0; j < 2; ++j) {
        int unit = tid + j * 512;
        int row = unit >> 2, u = unit & 3;
        cpa16(dst + OFF_B + swz_off(row, u),
              g_B + (size_t)(nbase + row) * K_DIM + k0 + u * 8);
    }
    cpa_commit();
}

__global__ __launch_bounds__(512) void indgru_gemm_mma() {
    extern __shared__ __align__(128) char smem[];
    const uint32_t sb = smem_u32(smem);
    const int tid = threadIdx.x;
    const int wid = tid >> 5;
    const int lid = tid & 31;
    const int mbase = blockIdx.x * GBM;
    const int nbase = blockIdx.y * GBN;

    const int m_warp = (wid >> 3) * 64;    // 0 or 64
    const int n_warp = (wid & 7) * 32;     // 0..224

    // ldmatrix per-lane row + unit components (swizzled at use)
    const int rowA = m_warp + (lid & 7) + ((lid >> 3) & 1) * 8;
    const int uA = (lid >> 4) & 1;               // + ks*2
    const int rowBm = n_warp + (lid & 7) + ((lid >> 4) & 1) * 8;
    const int uB = (lid >> 3) & 1;               // + ks*2

    float c[4][4][4];
#pragma unroll
    for (int i = 0; i < 4; ++i)
#pragma unroll
        for (int j = 0; j < 4; ++j)
#pragma unroll
            for (int q = 0; q < 4; ++q) c[i][j][q] = 0.f;

    load_stage(sb, 0, 0, mbase, nbase, tid);
    load_stage(sb, 1, 1, mbase, nbase, tid);
    load_stage(sb, 2, 2, mbase, nbase, tid);

    for (int kt = 0; kt < NSTEPS; ++kt) {
        const int stage = kt & (NSTAGE - 1);
        cpa_wait<2>();
        __syncthreads();   // stage kt ready; stage kt-1 fully consumed

        if (kt + 3 < NSTEPS)
            load_stage(sb, (kt + 3) & (NSTAGE - 1), kt + 3, mbase, nbase, tid);

        const uint32_t st = sb + stage * STAGE_BYTES;
#pragma unroll
        for (int ks = 0; ks < 2; ++ks) {
            uint32_t Ah[4][4], Bf[2][4];
#pragma unroll
            for (int mf = 0; mf < 4; ++mf)
                ldm4(Ah[mf], st + OFF_A + swz_off(rowA + mf * 16, uA + ks * 2));
#pragma unroll
            for (int nfp = 0; nfp < 2; ++nfp)
                ldm4(Bf[nfp], st + OFF_B + swz_off(rowBm + nfp * 16, uB + ks * 2));
#pragma unroll
            for (int mf = 0; mf < 4; ++mf)
#pragma unroll
                for (int nfp = 0; nfp < 2; ++nfp)
#pragma unroll
                    for (int hf = 0; hf < 2; ++hf)
                        mma_f16(c[mf][nfp * 2 + hf], Ah[mf], &Bf[nfp][hf * 2]);
        }
    }

    // epilogue: c[mf][nf] -> g_gx
    const int g = lid >> 2, t4 = lid & 3;
#pragma unroll
    for (int mf = 0; mf < 4; ++mf) {
        const int m0 = mbase + m_warp + mf * 16 + g;
        float* r0 = g_gx + (size_t)m0 * N_DIM + nbase + n_warp;
        float* r1 = r0 + (size_t)8 * N_DIM;
#pragma unroll
        for (int nf = 0; nf < 4; ++nf) {
            const int nc = nf * 8 + 2 * t4;
            *reinterpret_cast<float2*>(r0 + nc) =
                make_float2(c[mf][nf][0], c[mf][nf][1]);
            *reinterpret_cast<float2*>(r1 + nc) =
                make_float2(c[mf][nf][2], c[mf][nf][3]);
        }
    }
}

// ---------------------------------------------------------------------------
// Scan: one thread per (b, h); 512 blocks x 32 threads (1 warp/block, spreads
// ~1 warp per SMSP). Depth-16 RAW prefetch ring: loads issued ~16 chain-times
// (~1.5k cyc) before use -> covers loaded DRAM latency. Folded ex2/rcp math.
// ---------------------------------------------------------------------------
#define C_NL2E (-1.44269504088896f)   // -log2 e
#define C_2L2E (2.88539008177793f)    // 2 log2 e
#define SCAN_PF 16

__global__ __launch_bounds__(32)
void indgru_scan(const float* __restrict__ h0, const float* __restrict__ w_hh,
                 float* __restrict__ out) {
    const int idx = blockIdx.x * 32 + threadIdx.x;    // 0..16383
    const int b = idx >> 9;
    const int h = idx & (H_DIM - 1);

    const float nwr = C_NL2E * w_hh[h];
    const float nwz = C_NL2E * w_hh[H_DIM + h];
    const float wn2 = C_2L2E * w_hh[2 * H_DIM + h];

    float hv = h0[idx];

    const float* gbase = g_gx + (size_t)b * N_DIM + h;
    const int TSTRIDE = B_DIM * N_DIM;                // 49152

    float bgr[SCAN_PF], bgz[SCAN_PF], bgn[SCAN_PF];   // raw loads
#pragma unroll
    for (int i = 0; i < SCAN_PF; ++i) {
        const float* gp = gbase + (size_t)i * TSTRIDE;
        bgr[i] = __ldcs(gp);
        bgz[i] = __ldcs(gp + H_DIM);
        bgn[i] = __ldcs(gp + 2 * H_DIM);
    }

    float* op = out + idx;

#pragma unroll 16
    for (int t = 0; t < T_DIM; ++t) {
        const int s = t & (SCAN_PF - 1);
        const float gr = bgr[s], gz = bgz[s], gn = bgn[s];

        const int tp = t + SCAN_PF;
        if (tp < T_DIM) {
            const float* gp = gbase + (size_t)tp * TSTRIDE;
            bgr[s] = __ldcs(gp);
            bgz[s] = __ldcs(gp + H_DIM);
            bgn[s] = __ldcs(gp + 2 * H_DIM);
        }

        // scaled gate biases: off the dependent chain (data long-arrived)
        const float ngr = C_NL2E * gr;
        const float ngz = C_NL2E * gz;
        const float gn2 = C_2L2E * gn;

        // r = sigmoid(gr + wr*h) = 1/(1 + 2^(nwr*h + ngr))
        const float er = ex2f(fmaf(nwr, hv, ngr));
        const float r  = rcpf(1.f + er);
        const float ez = ex2f(fmaf(nwz, hv, ngz));
        const float z  = rcpf(1.f + ez);
        // n = tanh(gn + r*wn*h) = 1 - 2/(2^(2l2e*(gn + r*wn*h)) + 1)
        const float wnh2 = wn2 * hv;                  // off-chain vs r
        const float e2 = ex2f(fmaf(r, wnh2, gn2));
        const float n  = fmaf(-2.f, rcpf(1.f + e2), 1.f);
        hv = fmaf(z, hv - n, n);

        __stcs(op + (size_t)t * (B_DIM * H_DIM), hv);
    }
    __stcs(op + (size_t)T_DIM * (B_DIM * H_DIM), hv);
}

// ---------------------------------------------------------------------------
extern "C" void kernel_launch(void* const* d_in, const int* in_sizes, int n_in,
                              void* d_out, int out_size) {
    const float* x    = (const float*)d_in[0];   // (T, B, I)
    const float* h0   = (const float*)d_in[1];   // (B, H)
    const float* W_ih = (const float*)d_in[2];   // (3H, I)
    const float* w_hh = (const float*)d_in[3];   // (3, H)
    float* out = (float*)d_out;

    convert_A<<<1024, 256>>>((const float4*)x);
    convert_B<<<768, 256>>>((const float4*)W_ih);

    cudaFuncSetAttribute(indgru_gemm_mma,
                         cudaFuncAttributeMaxDynamicSharedMemorySize, GEMM_SMEM);
    dim3 grid(M_DIM / GBM, N_DIM / GBN);   // 128 x 6
    indgru_gemm_mma<<<grid, 512, GEMM_SMEM>>>();

    indgru_scan<<<(B_DIM * H_DIM) / 32, 32>>>(h0, w_hh, out);
}